// round 6
// baseline (speedup 1.0000x reference)
#include <cuda_runtime.h>
#include <math.h>

// BezierRenderer: 16 batches, 512x512, 10 segments.
// K1 fill_setup <<<528, 256>>>:
//    blocks 16..527: zero-fill the whole 16MB output (32KB/block, no loads)
//    blocks 0..15:   per-batch segment params + tile masks + compacted worklist
// K2 render_active <<<1184, 256>>>: grid-stride over compacted active tiles
//    (64x16 px each, 4 px/thread). Inactive blocks exit after one 64B load.

#define NSEG    10
#define NBATCH  16
#define SIZEI   512

struct SegParams {
    float4 seg[NSEG];        // {vy, vx, dy, dx}
    float  id2[NSEG];
    float  thick, invthick;
};

__device__ SegParams g_params[NBATCH];
__device__ unsigned int g_cnt[NBATCH];          // active tiles per batch
__device__ unsigned int g_list[NBATCH * 256];   // (mask<<16) | tile_tid

#define ZERO_BLOCKS 512
#define RENDER_BLOCKS 1184                      // 148 SMs * 8

// ---------------------------------------------------------------------------
// K1: zero-fill + setup
// ---------------------------------------------------------------------------
__global__ void __launch_bounds__(256)
fill_setup_kernel(const float* __restrict__ traj,
                  const float* __restrict__ thk,
                  float* __restrict__ out)
{
    const int tid = threadIdx.x;

    if (blockIdx.x >= NBATCH) {
        // ---- zero-fill: 512 blocks x 32KB, pure stores ----
        const int zb = blockIdx.x - NBATCH;            // 0..511
        float4* p = reinterpret_cast<float4*>(out) + (size_t)zb * 2048;
        const float4 z = make_float4(0.f, 0.f, 0.f, 0.f);
#pragma unroll
        for (int k = 0; k < 8; k++)
            p[k * 256 + tid] = z;
        return;
    }

    // ---- setup for batch b ----
    __shared__ float s_py[NSEG + 1], s_px[NSEG + 1];
    __shared__ float s_vy[NSEG], s_vx[NSEG], s_dy[NSEG], s_dx[NSEG], s_id2[NSEG];
    __shared__ float s_thick;
    __shared__ unsigned int s_n;

    const int b = blockIdx.x;

    if (tid <= NSEG) {
        float sy, sx;
        if (tid < NSEG) {
            const int start[4] = {10, 6, 3, 0};
            sy = 0.f; sx = 0.f;
#pragma unroll
            for (int i = 0; i < 4; i++) {
                float n = (float)(start[i] + tid) - 9.5f;
                float w = 0.75f * expf(-0.125f * n * n);   // exp(-0.5*(n/2)^2)
                sy += traj[b * 8 + i]     * w;
                sx += traj[b * 8 + 4 + i] * w;
            }
        } else {
            sy = traj[b * 8 + 3];
            sx = traj[b * 8 + 7];
        }
        s_py[tid] = sy * 512.f;
        s_px[tid] = sx * 512.f;
    }
    if (tid == 0) {
        float th = 0.f;
#pragma unroll
        for (int k = 0; k < 4; k++) th += thk[b * 4 + k] * 2.f + 0.5f;
        float t2 = 2.f * th;
        s_thick = t2;
        s_n = 0;
        g_params[b].thick    = t2;
        g_params[b].invthick = 1.f / t2;
    }
    __syncthreads();

    if (tid < NSEG) {
        float vy = s_py[tid], vx = s_px[tid];
        float dy = s_py[tid + 1] - vy;
        float dx = s_px[tid + 1] - vx;
        float id2 = 1.f / (dy * dy + dx * dx + 1e-5f);
        s_vy[tid] = vy;  s_vx[tid] = vx;
        s_dy[tid] = dy;  s_dx[tid] = dx;
        s_id2[tid] = id2;
        g_params[b].seg[tid] = make_float4(vy, vx, dy, dx);
        g_params[b].id2[tid] = id2;
    }
    __syncthreads();

    // One tile per thread: tx = tid>>5 (0..7), ty = tid&31 (0..31). Tile 64x16.
    // Center (tx*64+31.5, ty*16+7.5); max px-to-center dist sqrt(31.5^2+7.5^2)
    // = 32.38 < 33. Segment in mask iff dist(center,seg) < thick + 33.
    const float cx = (float)((tid >> 5) << 6) + 31.5f;
    const float cy = (float)((tid & 31) << 4) + 7.5f;
    const float lim = s_thick + 33.0f;
    const float lim2 = lim * lim;

    unsigned int m = 0;
#pragma unroll
    for (int j = 0; j < NSEG; j++) {
        float ay = cy - s_vy[j];
        float ax = cx - s_vx[j];
        float dot = ay * s_dy[j] + ax * s_dx[j];
        float t = fminf(fmaxf(dot * s_id2[j], 0.f), 1.f);
        float ry = fmaf(-t, s_dy[j], ay);
        float rx = fmaf(-t, s_dx[j], ax);
        if (fmaf(ry, ry, rx * rx) < lim2) m |= (1u << j);
    }

    // Compact active tiles of this batch (order within list is irrelevant:
    // each tile is written exactly once by K2).
    if (m) {
        unsigned int slot = atomicAdd(&s_n, 1u);
        g_list[b * 256 + slot] = (m << 16) | (unsigned int)tid;
    }
    __syncthreads();
    if (tid == 0) g_cnt[b] = s_n;
}

// ---------------------------------------------------------------------------
// K2: render active tiles. Grid-stride over sum of per-batch counts.
// ---------------------------------------------------------------------------
__global__ void __launch_bounds__(256)
render_active_kernel(float* __restrict__ out)
{
    const int tid = threadIdx.x;

    // Load 16 counts (64B, uniform, L2-broadcast).
    const uint4 c0 = __ldg(reinterpret_cast<const uint4*>(&g_cnt[0]));
    const uint4 c1 = __ldg(reinterpret_cast<const uint4*>(&g_cnt[4]));
    const uint4 c2 = __ldg(reinterpret_cast<const uint4*>(&g_cnt[8]));
    const uint4 c3 = __ldg(reinterpret_cast<const uint4*>(&g_cnt[12]));
    unsigned int cnt[NBATCH] = {c0.x, c0.y, c0.z, c0.w, c1.x, c1.y, c1.z, c1.w,
                                c2.x, c2.y, c2.z, c2.w, c3.x, c3.y, c3.z, c3.w};
    unsigned int total = 0;
#pragma unroll
    for (int i = 0; i < NBATCH; i++) total += cnt[i];

    for (unsigned int w = blockIdx.x; w < total; w += RENDER_BLOCKS) {
        // locate batch + index within batch
        unsigned int acc = 0;
        int b = 0;
        unsigned int idx = 0;
#pragma unroll
        for (int i = 0; i < NBATCH; i++) {
            if (w >= acc && w < acc + cnt[i]) { b = i; idx = w - acc; }
            acc += cnt[i];
        }

        const unsigned int entry = __ldg(&g_list[b * 256 + idx]);
        unsigned int mask = entry >> 16;
        const int ttid = (int)(entry & 0xFFu);
        const int tx = ttid >> 5, ty = ttid & 31;

        const int x = (tx << 6) + (tid & 15) * 4;
        const int y = (ty << 4) + (tid >> 4);
        float* outp = out + ((size_t)b << 18) + ((size_t)y << 9) + x;

        const SegParams* sp = &g_params[b];
        const float thick    = __ldg(&sp->thick);
        const float invthick = __ldg(&sp->invthick);

        const float yf = (float)y;
        const float x0 = (float)x;

        float m0 = 1e30f, m1 = 1e30f, m2 = 1e30f, m3 = 1e30f;

        while (mask) {
            const int j = __ffs(mask) - 1;
            mask &= mask - 1;

            const float4 s  = __ldg(&sp->seg[j]);   // {vy, vx, dy, dx}
            const float ij  = __ldg(&sp->id2[j]);
            const float vjx = s.y, djy = s.z, djx = s.w;

            const float ay  = yf - s.x;
            const float cyd = ay * djy;

            {
                float pvx = x0 - vjx;
                float dot = fmaf(pvx, djx, cyd);
                float t   = fminf(fmaxf(dot * ij, 0.f), 1.f);
                float ry  = fmaf(-t, djy, ay);
                float rx  = fmaf(-t, djx, pvx);
                m0 = fminf(m0, fmaf(ry, ry, rx * rx));
            }
            {
                float pvx = x0 + 1.f - vjx;
                float dot = fmaf(pvx, djx, cyd);
                float t   = fminf(fmaxf(dot * ij, 0.f), 1.f);
                float ry  = fmaf(-t, djy, ay);
                float rx  = fmaf(-t, djx, pvx);
                m1 = fminf(m1, fmaf(ry, ry, rx * rx));
            }
            {
                float pvx = x0 + 2.f - vjx;
                float dot = fmaf(pvx, djx, cyd);
                float t   = fminf(fmaxf(dot * ij, 0.f), 1.f);
                float ry  = fmaf(-t, djy, ay);
                float rx  = fmaf(-t, djx, pvx);
                m2 = fminf(m2, fmaf(ry, ry, rx * rx));
            }
            {
                float pvx = x0 + 3.f - vjx;
                float dot = fmaf(pvx, djx, cyd);
                float t   = fminf(fmaxf(dot * ij, 0.f), 1.f);
                float ry  = fmaf(-t, djy, ay);
                float rx  = fmaf(-t, djx, pvx);
                m3 = fminf(m3, fmaf(ry, ry, rx * rx));
            }
        }

        float4 res;
        res.x = fminf(fmaxf((thick - sqrtf(m0)) * invthick, 0.f), 1.f);
        res.y = fminf(fmaxf((thick - sqrtf(m1)) * invthick, 0.f), 1.f);
        res.z = fminf(fmaxf((thick - sqrtf(m2)) * invthick, 0.f), 1.f);
        res.w = fminf(fmaxf((thick - sqrtf(m3)) * invthick, 0.f), 1.f);
        *reinterpret_cast<float4*>(outp) = res;
    }
}

extern "C" void kernel_launch(void* const* d_in, const int* in_sizes, int n_in,
                              void* d_out, int out_size)
{
    const float* traj = (const float*)d_in[0];   // (16, 2, 4)
    const float* thk  = (const float*)d_in[1];   // (16, 1, 4)
    float* out = (float*)d_out;                  // (16, 512, 512)

    fill_setup_kernel<<<NBATCH + ZERO_BLOCKS, 256>>>(traj, thk, out);
    render_active_kernel<<<RENDER_BLOCKS, 256>>>(out);
}

// round 7
// speedup vs baseline: 1.2112x; 1.2112x over previous
#include <cuda_runtime.h>
#include <math.h>

// BezierRenderer: 16 batches, 512x512, 10 segments.
//  K1 setup <<<16, 256>>>: per-batch segment params + per-tile segment masks.
//  K2 render <<<(8,32,16), 256>>>: launched with PDL (programmatic stream
//     serialization). Each block: speculative zero store (independent of K1),
//     then cudaGridDependencySynchronize(), then mask-driven render.
// Tile = 64x16 px, 4 px (float4) per thread.

#define NSEG    10
#define NBATCH  16
#define TILES_X 8
#define TILES_Y 32
#define TILES_PER_BATCH (TILES_X * TILES_Y)   // 256
#define NTILES  (TILES_PER_BATCH * NBATCH)    // 4096
#define SIZEI   512

struct SegParams {
    float4 seg[NSEG];        // {vy, vx, dy, dx}
    float  id2[NSEG];
    float  thick, invthick;
};

__device__ SegParams g_params[NBATCH];
__device__ unsigned int g_mask[NTILES];

// ---------------------------------------------------------------------------
// K1: setup. One block per batch: stroke points, segment params, tile masks.
// ---------------------------------------------------------------------------
__global__ void __launch_bounds__(256)
setup_kernel(const float* __restrict__ traj,
             const float* __restrict__ thk)
{
    __shared__ float s_py[NSEG + 1], s_px[NSEG + 1];
    __shared__ float s_vy[NSEG], s_vx[NSEG], s_dy[NSEG], s_dx[NSEG], s_id2[NSEG];
    __shared__ float s_thick;

    const int b   = blockIdx.x;
    const int tid = threadIdx.x;

    if (tid <= NSEG) {
        float sy, sx;
        if (tid < NSEG) {
            const int start[4] = {10, 6, 3, 0};
            sy = 0.f; sx = 0.f;
#pragma unroll
            for (int i = 0; i < 4; i++) {
                float n = (float)(start[i] + tid) - 9.5f;
                float w = 0.75f * expf(-0.125f * n * n);   // exp(-0.5*(n/2)^2)
                sy += traj[b * 8 + i]     * w;
                sx += traj[b * 8 + 4 + i] * w;
            }
        } else {
            sy = traj[b * 8 + 3];
            sx = traj[b * 8 + 7];
        }
        s_py[tid] = sy * 512.f;
        s_px[tid] = sx * 512.f;
    }
    if (tid == 0) {
        float th = 0.f;
#pragma unroll
        for (int k = 0; k < 4; k++) th += thk[b * 4 + k] * 2.f + 0.5f;
        float t2 = 2.f * th;
        s_thick = t2;
        g_params[b].thick    = t2;
        g_params[b].invthick = 1.f / t2;
    }
    __syncthreads();

    if (tid < NSEG) {
        float vy = s_py[tid], vx = s_px[tid];
        float dy = s_py[tid + 1] - vy;
        float dx = s_px[tid + 1] - vx;
        float id2 = 1.f / (dy * dy + dx * dx + 1e-5f);
        s_vy[tid] = vy;  s_vx[tid] = vx;
        s_dy[tid] = dy;  s_dx[tid] = dx;
        s_id2[tid] = id2;
        g_params[b].seg[tid] = make_float4(vy, vx, dy, dx);
        g_params[b].id2[tid] = id2;
    }
    __syncthreads();

    // One tile per thread: tile (tx, ty) = (tid & 7, tid >> 3), tile 64x16.
    // Center (tx*64+31.5, ty*16+7.5); max pixel-to-center distance
    // sqrt(31.5^2+7.5^2)=32.38 < 33. Segment in mask iff dist(center,seg)<thick+33.
    const float cx = (float)((tid & 7) << 6) + 31.5f;
    const float cy = (float)((tid >> 3) << 4) + 7.5f;
    const float lim = s_thick + 33.0f;
    const float lim2 = lim * lim;

    unsigned int m = 0;
#pragma unroll
    for (int j = 0; j < NSEG; j++) {
        float ay = cy - s_vy[j];
        float ax = cx - s_vx[j];
        float dot = ay * s_dy[j] + ax * s_dx[j];
        float t = fminf(fmaxf(dot * s_id2[j], 0.f), 1.f);
        float ry = fmaf(-t, s_dy[j], ay);
        float rx = fmaf(-t, s_dx[j], ax);
        if (fmaf(ry, ry, rx * rx) < lim2) m |= (1u << j);
    }
    g_mask[b * TILES_PER_BATCH + tid] = m;
}

// ---------------------------------------------------------------------------
// K2: render. Speculative zero store first (no dependency on K1), then wait
// on the PDL grid dependency, then mask-driven recompute of active tiles.
// ---------------------------------------------------------------------------
__global__ void __launch_bounds__(256)
render_kernel(float* __restrict__ out)
{
    const int b   = blockIdx.z;
    const int tid = threadIdx.x;
    const int tile_id = b * TILES_PER_BATCH + blockIdx.y * TILES_X + blockIdx.x;

    const int x = (blockIdx.x << 6) + (tid & 15) * 4;
    const int y = (blockIdx.y << 4) + (tid >> 4);
    float* outp = out + ((size_t)b << 18) + ((size_t)y << 9) + x;

    // Speculative zero fill — independent of setup, issues immediately.
    *reinterpret_cast<float4*>(outp) = make_float4(0.f, 0.f, 0.f, 0.f);

    // Wait for setup_kernel's results (PDL).
    cudaGridDependencySynchronize();

    unsigned int mask = __ldg(&g_mask[tile_id]);          // uniform across block
    if (mask == 0) return;

    const SegParams* sp = &g_params[b];
    const float thick    = __ldg(&sp->thick);
    const float invthick = __ldg(&sp->invthick);

    const float yf = (float)y;
    const float x0 = (float)x;

    float m0 = 1e30f, m1 = 1e30f, m2 = 1e30f, m3 = 1e30f;

    while (mask) {
        const int j = __ffs(mask) - 1;
        mask &= mask - 1;

        const float4 s  = __ldg(&sp->seg[j]);   // {vy, vx, dy, dx}
        const float ij  = __ldg(&sp->id2[j]);
        const float vjx = s.y, djy = s.z, djx = s.w;

        const float ay  = yf - s.x;            // same for all 4 px (same row)
        const float cyd = ay * djy;

        {
            float pvx = x0 - vjx;
            float dot = fmaf(pvx, djx, cyd);
            float t   = fminf(fmaxf(dot * ij, 0.f), 1.f);
            float ry  = fmaf(-t, djy, ay);
            float rx  = fmaf(-t, djx, pvx);
            m0 = fminf(m0, fmaf(ry, ry, rx * rx));
        }
        {
            float pvx = x0 + 1.f - vjx;
            float dot = fmaf(pvx, djx, cyd);
            float t   = fminf(fmaxf(dot * ij, 0.f), 1.f);
            float ry  = fmaf(-t, djy, ay);
            float rx  = fmaf(-t, djx, pvx);
            m1 = fminf(m1, fmaf(ry, ry, rx * rx));
        }
        {
            float pvx = x0 + 2.f - vjx;
            float dot = fmaf(pvx, djx, cyd);
            float t   = fminf(fmaxf(dot * ij, 0.f), 1.f);
            float ry  = fmaf(-t, djy, ay);
            float rx  = fmaf(-t, djx, pvx);
            m2 = fminf(m2, fmaf(ry, ry, rx * rx));
        }
        {
            float pvx = x0 + 3.f - vjx;
            float dot = fmaf(pvx, djx, cyd);
            float t   = fminf(fmaxf(dot * ij, 0.f), 1.f);
            float ry  = fmaf(-t, djy, ay);
            float rx  = fmaf(-t, djx, pvx);
            m3 = fminf(m3, fmaf(ry, ry, rx * rx));
        }
    }

    float4 res;
    res.x = fminf(fmaxf((thick - sqrtf(m0)) * invthick, 0.f), 1.f);
    res.y = fminf(fmaxf((thick - sqrtf(m1)) * invthick, 0.f), 1.f);
    res.z = fminf(fmaxf((thick - sqrtf(m2)) * invthick, 0.f), 1.f);
    res.w = fminf(fmaxf((thick - sqrtf(m3)) * invthick, 0.f), 1.f);

    *reinterpret_cast<float4*>(outp) = res;
}

extern "C" void kernel_launch(void* const* d_in, const int* in_sizes, int n_in,
                              void* d_out, int out_size)
{
    const float* traj = (const float*)d_in[0];   // (16, 2, 4)
    const float* thk  = (const float*)d_in[1];   // (16, 1, 4)
    float* out = (float*)d_out;                  // (16, 512, 512)

    setup_kernel<<<NBATCH, 256>>>(traj, thk);

    // Render with Programmatic Dependent Launch: starts concurrently with
    // setup; the kernel itself waits (cudaGridDependencySynchronize) only
    // before reading setup's outputs.
    cudaLaunchConfig_t cfg = {};
    cfg.gridDim  = dim3(TILES_X, TILES_Y, NBATCH);   // (8, 32, 16)
    cfg.blockDim = dim3(256, 1, 1);
    cfg.dynamicSmemBytes = 0;
    cfg.stream = 0;

    cudaLaunchAttribute attr[1];
    attr[0].id = cudaLaunchAttributeProgrammaticStreamSerialization;
    attr[0].val.programmaticStreamSerializationAllowed = 1;
    cfg.attrs = attr;
    cfg.numAttrs = 1;

    cudaLaunchKernelEx(&cfg, render_kernel, out);
}